// round 1
// baseline (speedup 1.0000x reference)
#include <cuda_runtime.h>
#include <cstddef>

#define B_   16
#define C_   64
#define HW_  96
#define CC   8      // ci chunk per smem stage

// ---------------- scratch (static device globals: allocation-rule safe) ------
__device__ float g_kf[(size_t)B_ * C_ * HW_ * HW_];
__device__ float g_qf[(size_t)B_ * C_ * HW_ * HW_];
__device__ float g_vf[(size_t)B_ * C_ * HW_ * HW_];
__device__ float g_sc[(size_t)B_ * C_ * 576];

// ---------------- 3x3 same-pad conv (correlation), 16x16 spatial tile --------
// out[b,co,y,x] = sum_{ci,kh,kw} xin[b,ci,y+kh-1,x+kw-1] * w[co, ci*9 + kh*3 + kw]
// w base = wgt + b*wBatchStride  (0 for static weights, 64*576 for dynamic attn)
__global__ __launch_bounds__(256, 2) void conv3x3_k(
    const float* __restrict__ xin, const float* __restrict__ wgt,
    float* __restrict__ out, int wBatchStride)
{
    __shared__ float sin_[CC * 18 * 18];                 // input tile + halo
    __shared__ __align__(16) float wsm[C_ * CC * 12];    // [co][ci][12] (9 used, padded for LDS.128)

    const int b  = blockIdx.z;
    const int bx = blockIdx.x * 16, by = blockIdx.y * 16;
    const int t  = threadIdx.x;
    const int tx = t & 15, ty = t >> 4;

    const float* xb = xin + (size_t)b * C_ * HW_ * HW_;
    const float* wb = wgt + (size_t)b * wBatchStride;

    float acc[C_];
#pragma unroll
    for (int i = 0; i < C_; i++) acc[i] = 0.f;

#pragma unroll 1
    for (int c0 = 0; c0 < C_; c0 += CC) {
        __syncthreads();
        // stage input tile (CC x 18 x 18, zero-padded at image border)
        for (int idx = t; idx < CC * 18 * 18; idx += 256) {
            int ci = idx / 324, rem = idx % 324;
            int r = rem / 18, cx = rem % 18;
            int gy = by + r - 1, gx = bx + cx - 1;
            float v = 0.f;
            if (gy >= 0 && gy < HW_ && gx >= 0 && gx < HW_)
                v = xb[((size_t)(c0 + ci) * HW_ + gy) * HW_ + gx];
            sin_[idx] = v;
        }
        // stage weights: wsm[co][ci][k], k padded 9 -> 12 for aligned float4 reads
        for (int idx = t; idx < C_ * CC * 12; idx += 256) {
            int k = idx % 12, rest = idx / 12;
            int ci = rest % CC, co = rest / CC;
            float v = 0.f;
            if (k < 9) v = wb[co * 576 + (c0 + ci) * 9 + k];
            wsm[idx] = v;
        }
        __syncthreads();

#pragma unroll 1
        for (int ci = 0; ci < CC; ci++) {
            const float* sp = sin_ + ci * 324 + ty * 18 + tx;
            float v0 = sp[0],  v1 = sp[1],  v2 = sp[2];
            float v3 = sp[18], v4 = sp[19], v5 = sp[20];
            float v6 = sp[36], v7 = sp[37], v8 = sp[38];
#pragma unroll
            for (int co = 0; co < C_; co++) {
                const float4* w = (const float4*)(wsm + (co * CC + ci) * 12);
                float4 a = w[0], bq = w[1], cq = w[2];
                acc[co] += v0 * a.x + v1 * a.y + v2 * a.z
                         + v3 * a.w + v4 * bq.x + v5 * bq.y
                         + v6 * bq.z + v7 * bq.w + v8 * cq.x;
            }
        }
    }

    float* ob = out + ((size_t)(b * C_) * HW_ + (by + ty)) * HW_ + bx + tx;
#pragma unroll
    for (int co = 0; co < C_; co++)
        ob[(size_t)co * HW_ * HW_] = acc[co];
}

// ---------------- scores: per (b,k) 64x64 Gram over the k-th pixel class -----
// scores[b,k,c,d] = sum_{hp,wp} kf[b,c,hp*3+kh,wp*3+kw] * qf[b,d,hp*3+kh,wp*3+kw]
// stored scaled as sc[b][d][c*9+k] (softmax-ready layout)
__global__ __launch_bounds__(256) void scores_k(
    const float* __restrict__ kf, const float* __restrict__ qf,
    float* __restrict__ sc)
{
    __shared__ float ks[C_][33];
    __shared__ float qs[C_][33];

    const int bk = blockIdx.x;
    const int b = bk / 9, k = bk - b * 9;
    const int kh = k / 3, kw = k - kh * 3;
    const int t = threadIdx.x;
    const int tc = t >> 4, td = t & 15;   // c-group, d-group

    const float* kb = kf + (size_t)b * C_ * HW_ * HW_;
    const float* qb = qf + (size_t)b * C_ * HW_ * HW_;

    float acc[4][4] = {};

#pragma unroll 1
    for (int hp = 0; hp < 32; hp++) {
        __syncthreads();
        const int y = hp * 3 + kh;
        for (int idx = t; idx < C_ * 32; idx += 256) {
            int c = idx >> 5, wp = idx & 31;
            int x = wp * 3 + kw;
            size_t off = ((size_t)c * HW_ + y) * HW_ + x;
            ks[c][wp] = kb[off];
            qs[c][wp] = qb[off];
        }
        __syncthreads();
#pragma unroll 4
        for (int l = 0; l < 32; l++) {
            float kv[4], qv[4];
#pragma unroll
            for (int i = 0; i < 4; i++) { kv[i] = ks[tc * 4 + i][l]; qv[i] = qs[td * 4 + i][l]; }
#pragma unroll
            for (int i = 0; i < 4; i++)
#pragma unroll
                for (int j = 0; j < 4; j++)
                    acc[i][j] += kv[i] * qv[j];
        }
    }

    const float scale = 1.f / 24.f;   // 1/sqrt(COUT*aa) = 1/sqrt(576)
#pragma unroll
    for (int j = 0; j < 4; j++)
#pragma unroll
        for (int i = 0; i < 4; i++) {
            int d = td * 4 + j, c = tc * 4 + i;
            sc[((size_t)(b * C_ + d) * C_ + c) * 9 + k] = acc[i][j] * scale;
        }
}

// ---------------- softmax over 576 per (b,d) row, in place -------------------
__global__ __launch_bounds__(256) void softmax_k(float* __restrict__ s)
{
    __shared__ float red[8];
    float* p = s + (size_t)blockIdx.x * 576;
    const int t = threadIdx.x;

    float v0 = p[t];
    float v1 = p[t + 256];
    bool has2 = (t + 512) < 576;
    float v2 = has2 ? p[t + 512] : -3.4e38f;

    float m = fmaxf(fmaxf(v0, v1), v2);
#pragma unroll
    for (int o = 16; o; o >>= 1) m = fmaxf(m, __shfl_xor_sync(0xffffffffu, m, o));
    if ((t & 31) == 0) red[t >> 5] = m;
    __syncthreads();
    m = fmaxf(fmaxf(fmaxf(red[0], red[1]), fmaxf(red[2], red[3])),
              fmaxf(fmaxf(red[4], red[5]), fmaxf(red[6], red[7])));
    __syncthreads();

    float e0 = __expf(v0 - m), e1 = __expf(v1 - m);
    float e2 = has2 ? __expf(v2 - m) : 0.f;
    float sum = e0 + e1 + e2;
#pragma unroll
    for (int o = 16; o; o >>= 1) sum += __shfl_xor_sync(0xffffffffu, sum, o);
    if ((t & 31) == 0) red[t >> 5] = sum;
    __syncthreads();
    sum = red[0] + red[1] + red[2] + red[3] + red[4] + red[5] + red[6] + red[7];

    float inv = 1.f / sum;
    p[t] = e0 * inv;
    p[t + 256] = e1 * inv;
    if (has2) p[t + 512] = e2 * inv;
}

// ---------------- launch -----------------------------------------------------
extern "C" void kernel_launch(void* const* d_in, const int* in_sizes, int n_in,
                              void* d_out, int out_size)
{
    const float* x1 = (const float*)d_in[0];
    const float* x2 = (const float*)d_in[1];
    const float* w1 = (const float*)d_in[2];
    const float* w2 = (const float*)d_in[3];
    const float* w3 = (const float*)d_in[4];
    float* out = (float*)d_out;

    float *kf, *qf, *vf, *sc;
    cudaGetSymbolAddress((void**)&kf, g_kf);
    cudaGetSymbolAddress((void**)&qf, g_qf);
    cudaGetSymbolAddress((void**)&vf, g_vf);
    cudaGetSymbolAddress((void**)&sc, g_sc);

    dim3 g(HW_ / 16, HW_ / 16, B_);
    dim3 blk(256, 1, 1);

    conv3x3_k<<<g, blk>>>(x1, w1, kf, 0);
    conv3x3_k<<<g, blk>>>(x2, w2, qf, 0);
    conv3x3_k<<<g, blk>>>(x1, w3, vf, 0);
    scores_k<<<B_ * 9, 256>>>(kf, qf, sc);
    softmax_k<<<B_ * C_, 256>>>(sc);
    conv3x3_k<<<g, blk>>>(vf, sc, out, C_ * 576);
}

// round 2
// speedup vs baseline: 1.5326x; 1.5326x over previous
#include <cuda_runtime.h>
#include <cstddef>

#define B_   16
#define C_   64
#define HW_  96
#define CC   8      // ci chunk per smem stage

typedef unsigned long long ull;

// ---------------- scratch (static device globals: allocation-rule safe) ------
__device__ float g_kf[(size_t)B_ * C_ * HW_ * HW_];
__device__ float g_qf[(size_t)B_ * C_ * HW_ * HW_];
__device__ float g_vf[(size_t)B_ * C_ * HW_ * HW_];
__device__ float g_sc[(size_t)B_ * C_ * 576];
__device__ float g_scp[(size_t)4 * B_ * 9 * 64 * 64];   // scores partials [ch][b][k][c][d]

// ---------------- packed fp32x2 helpers (sm_103a FFMA2) ----------------------
__device__ __forceinline__ ull pack2(float a, float b) {
    ull r; asm("mov.b64 %0, {%1, %2};" : "=l"(r) : "f"(a), "f"(b)); return r;
}
__device__ __forceinline__ void fma2(ull& d, ull a, ull b) {
    asm("fma.rn.f32x2 %0, %1, %2, %3;" : "=l"(d) : "l"(a), "l"(b), "l"(d));
}
__device__ __forceinline__ float2 unpack2(ull v) {
    float2 r; asm("mov.b64 {%0, %1}, %2;" : "=f"(r.x), "=f"(r.y) : "l"(v)); return r;
}

// ---------------- 3x3 same-pad conv, FFMA2 co-pair packed --------------------
// out[b,co,y,x] = sum_{ci,kh,kw} xin[b,ci,y+kh-1,x+kw-1] * w[co, ci*9+kh*3+kw]
// Thread: 4 horizontal pixels x 8 co-pairs (16 co). Block: 16x16 tile, all 64 co.
__global__ __launch_bounds__(256, 2) void conv3x3_k(
    const float* __restrict__ xin, const float* __restrict__ wgt,
    float* __restrict__ out, int wBatchStride)
{
    __shared__ float sin_[CC * 18 * 20];              // rows padded 18->20 (16B align)
    __shared__ __align__(16) ull wsm[CC * 32 * 3 * 4]; // [ci][copair][kh][4 pairs]

    const int b  = blockIdx.z;
    const int bx = blockIdx.x * 16, by = blockIdx.y * 16;
    const int t  = threadIdx.x;
    const int pg   = t >> 6;            // co-pair group (8 pairs each)
    const int slot = t & 63;
    const int lx   = (slot & 3) * 4;    // pixel-x base within tile
    const int py   = slot >> 2;         // pixel-y within tile

    const float* xb = xin + (size_t)b * C_ * HW_ * HW_;
    const float* wb = wgt + (size_t)b * wBatchStride;

    ull acc[8][4];
#pragma unroll
    for (int i = 0; i < 8; i++)
#pragma unroll
        for (int j = 0; j < 4; j++) acc[i][j] = 0ull;

#pragma unroll 1
    for (int c0 = 0; c0 < C_; c0 += CC) {
        __syncthreads();
        // stage input tile (CC x 18 x 18 into pitch-20 rows, zero-padded at border)
        for (int idx = t; idx < CC * 324; idx += 256) {
            int ci = idx / 324, rem = idx % 324;
            int r = rem / 18, cx = rem % 18;
            int gy = by + r - 1, gx = bx + cx - 1;
            float v = 0.f;
            if (gy >= 0 && gy < HW_ && gx >= 0 && gx < HW_)
                v = xb[((size_t)(c0 + ci) * HW_ + gy) * HW_ + gx];
            sin_[ci * 360 + r * 20 + cx] = v;
        }
        // stage weights dup-interleaved: wsm[ci][cp][kh][p] = (w[2cp][kh*3+p], w[2cp+1][kh*3+p])
        for (int idx = t; idx < CC * 32 * 12; idx += 256) {
            int p = idx & 3, q = idx >> 2;
            int kh = q % 3; q /= 3;
            int cp = q & 31; int ci = q >> 5;
            ull v = 0ull;
            if (p < 3) {
                int k = kh * 3 + p, co = cp * 2;
                v = pack2(wb[co * 576 + (c0 + ci) * 9 + k],
                          wb[(co + 1) * 576 + (c0 + ci) * 9 + k]);
            }
            wsm[idx] = v;
        }
        __syncthreads();

#pragma unroll 1
        for (int ci = 0; ci < CC; ci++) {
#pragma unroll
            for (int kh = 0; kh < 3; kh++) {
                const float* rp = sin_ + ci * 360 + (py + kh) * 20 + lx;
                float4 a = *(const float4*)rp;
                float2 bq = *(const float2*)(rp + 4);
                ull vv[6];
                vv[0] = pack2(a.x, a.x);  vv[1] = pack2(a.y, a.y);
                vv[2] = pack2(a.z, a.z);  vv[3] = pack2(a.w, a.w);
                vv[4] = pack2(bq.x, bq.x); vv[5] = pack2(bq.y, bq.y);
                const ull* wbase = wsm + ((ci * 32 + pg * 8) * 3 + kh) * 4;
#pragma unroll
                for (int cpl = 0; cpl < 8; cpl++) {
                    const ulonglong2* wpp = (const ulonglong2*)(wbase + cpl * 12);
                    ulonglong2 wA = wpp[0], wB = wpp[1];
#pragma unroll
                    for (int p = 0; p < 4; p++) {
                        fma2(acc[cpl][p], vv[p],     wA.x);
                        fma2(acc[cpl][p], vv[p + 1], wA.y);
                        fma2(acc[cpl][p], vv[p + 2], wB.x);
                    }
                }
            }
        }
    }

    const int y = by + py;
#pragma unroll
    for (int cpl = 0; cpl < 8; cpl++) {
        int co = (pg * 8 + cpl) * 2;
        float* o0 = out + (((size_t)(b * C_ + co)) * HW_ + y) * HW_ + bx + lx;
        float* o1 = o0 + (size_t)HW_ * HW_;
#pragma unroll
        for (int p = 0; p < 4; p++) {
            float2 v = unpack2(acc[cpl][p]);
            o0[p] = v.x;
            o1[p] = v.y;
        }
    }
}

// ---------------- scores partials: per (b,k,chunk) 64x64 Gram over 8 hp rows -
// scp[ch][b][k][c][d] = sum_{hp in chunk, wp} kf[b,c,hp*3+kh,wp*3+kw]*qf[b,d,...]
__global__ __launch_bounds__(256) void scores_k(
    const float* __restrict__ kf, const float* __restrict__ qf,
    float* __restrict__ scp)
{
    __shared__ float ks[C_][33];
    __shared__ float qs[C_][33];

    const int k  = blockIdx.x;          // 0..8
    const int ch = blockIdx.y;          // 0..3
    const int b  = blockIdx.z;          // 0..15
    const int kh = k / 3, kw = k - kh * 3;
    const int t = threadIdx.x;
    const int tc = t >> 4, td = t & 15;

    const float* kb = kf + (size_t)b * C_ * HW_ * HW_;
    const float* qb = qf + (size_t)b * C_ * HW_ * HW_;

    float acc[4][4] = {};

#pragma unroll 1
    for (int hp = ch * 8; hp < ch * 8 + 8; hp++) {
        __syncthreads();
        const int y = hp * 3 + kh;
        for (int idx = t; idx < C_ * 32; idx += 256) {
            int c = idx >> 5, wp = idx & 31;
            int x = wp * 3 + kw;
            size_t off = ((size_t)c * HW_ + y) * HW_ + x;
            ks[c][wp] = kb[off];
            qs[c][wp] = qb[off];
        }
        __syncthreads();
#pragma unroll 4
        for (int l = 0; l < 32; l++) {
            float kv[4], qv[4];
#pragma unroll
            for (int i = 0; i < 4; i++) { kv[i] = ks[tc * 4 + i][l]; qv[i] = qs[td * 4 + i][l]; }
#pragma unroll
            for (int i = 0; i < 4; i++)
#pragma unroll
                for (int j = 0; j < 4; j++)
                    acc[i][j] += kv[i] * qv[j];
        }
    }

    float* p = scp + ((size_t)((ch * 16 + b) * 9 + k)) * 4096;
#pragma unroll
    for (int i = 0; i < 4; i++)
#pragma unroll
        for (int j = 0; j < 4; j++)
            p[(tc * 4 + i) * 64 + (td * 4 + j)] = acc[i][j];
}

// ---------------- softmax over 576 per (b,d): sum partials, scale, softmax ---
__global__ __launch_bounds__(256) void softmax_k(
    const float* __restrict__ scp, float* __restrict__ s)
{
    __shared__ float red[8];
    const int b = blockIdx.x >> 6, d = blockIdx.x & 63;
    const int t = threadIdx.x;
    const float scale = 1.f / 24.f;     // 1/sqrt(576)

    float v[3];
#pragma unroll
    for (int u = 0; u < 3; u++) {
        int e = t + u * 256;
        if (e < 576) {
            int c = e / 9, k = e - c * 9;
            float sum = 0.f;
#pragma unroll
            for (int chn = 0; chn < 4; chn++)
                sum += scp[((size_t)((chn * 16 + b) * 9 + k)) * 4096 + c * 64 + d];
            v[u] = sum * scale;
        } else v[u] = -3.4e38f;
    }

    float m = fmaxf(fmaxf(v[0], v[1]), v[2]);
#pragma unroll
    for (int o = 16; o; o >>= 1) m = fmaxf(m, __shfl_xor_sync(0xffffffffu, m, o));
    if ((t & 31) == 0) red[t >> 5] = m;
    __syncthreads();
    m = fmaxf(fmaxf(fmaxf(red[0], red[1]), fmaxf(red[2], red[3])),
              fmaxf(fmaxf(red[4], red[5]), fmaxf(red[6], red[7])));
    __syncthreads();

    float e0 = __expf(v[0] - m), e1 = __expf(v[1] - m);
    float e2 = (t + 512) < 576 ? __expf(v[2] - m) : 0.f;
    float sum = e0 + e1 + e2;
#pragma unroll
    for (int o = 16; o; o >>= 1) sum += __shfl_xor_sync(0xffffffffu, sum, o);
    if ((t & 31) == 0) red[t >> 5] = sum;
    __syncthreads();
    sum = red[0] + red[1] + red[2] + red[3] + red[4] + red[5] + red[6] + red[7];

    float inv = 1.f / sum;
    float* p = s + (size_t)(b * C_ + d) * 576;
    p[t] = e0 * inv;
    p[t + 256] = e1 * inv;
    if (t + 512 < 576) p[t + 512] = e2 * inv;
}

// ---------------- launch -----------------------------------------------------
extern "C" void kernel_launch(void* const* d_in, const int* in_sizes, int n_in,
                              void* d_out, int out_size)
{
    const float* x1 = (const float*)d_in[0];
    const float* x2 = (const float*)d_in[1];
    const float* w1 = (const float*)d_in[2];
    const float* w2 = (const float*)d_in[3];
    const float* w3 = (const float*)d_in[4];
    float* out = (float*)d_out;

    float *kf, *qf, *vf, *sc, *scp;
    cudaGetSymbolAddress((void**)&kf, g_kf);
    cudaGetSymbolAddress((void**)&qf, g_qf);
    cudaGetSymbolAddress((void**)&vf, g_vf);
    cudaGetSymbolAddress((void**)&sc, g_sc);
    cudaGetSymbolAddress((void**)&scp, g_scp);

    dim3 g(HW_ / 16, HW_ / 16, B_);
    dim3 blk(256, 1, 1);

    conv3x3_k<<<g, blk>>>(x1, w1, kf, 0);
    conv3x3_k<<<g, blk>>>(x2, w2, qf, 0);
    conv3x3_k<<<g, blk>>>(x1, w3, vf, 0);
    scores_k<<<dim3(9, 4, B_), 256>>>(kf, qf, scp);
    softmax_k<<<B_ * C_, 256>>>(scp, sc);
    conv3x3_k<<<g, blk>>>(vf, sc, out, C_ * 576);
}